// round 1
// baseline (speedup 1.0000x reference)
#include <cuda_runtime.h>
#include <cuda_bf16.h>

#define D     64
#define C     256
#define C4    (C/4)          // 64 float4 per row
#define RDIM  128
#define NPTS  100000
#define PAD   3
#define GRID_VOX (D*D*D)     // 262144

// ---- scratch (device globals; no allocation allowed) ----
__device__ int    g_idx[GRID_VOX];                       // 1 MB: point index or -1
__device__ float4 g_bufA[(size_t)GRID_VOX * C4];         // 268 MB
__device__ float4 g_bufB[(size_t)GRID_VOX * C4];         // 268 MB
__device__ float  g_y[(size_t)NPTS * C];                 // 100 MB: pooled, compacted per point

__device__ __forceinline__ float4 vmax4(float4 a, float4 b) {
    return make_float4(fmaxf(a.x, b.x), fmaxf(a.y, b.y),
                       fmaxf(a.z, b.z), fmaxf(a.w, b.w));
}

__device__ __forceinline__ float4 neg_inf4() {
    const float ni = __int_as_float(0xff800000u);
    return make_float4(ni, ni, ni, ni);
}

// ---------------------------------------------------------------------------
// 1) index grid init + scatter
// ---------------------------------------------------------------------------
__global__ void init_idx_kernel() {
    int i = blockIdx.x * blockDim.x + threadIdx.x;
    if (i < GRID_VOX) g_idx[i] = -1;
}

__global__ void scatter_idx_kernel(const int* __restrict__ coords) {
    int n = blockIdx.x * blockDim.x + threadIdx.x;
    if (n < NPTS) {
        int ix = coords[3*n+0], iy = coords[3*n+1], iz = coords[3*n+2];
        g_idx[(ix*D + iy)*D + iz] = n;
    }
}

// ---------------------------------------------------------------------------
// 2) z-pass: read feats through index grid, sliding window-7 max along z
//    thread = (x,y) pair x c4; blockDim=(64,4)
// ---------------------------------------------------------------------------
__device__ __forceinline__ float4 load_point(const float* __restrict__ feats,
                                             int vox, int c4) {
    int idx = g_idx[vox];
    if (idx < 0) return neg_inf4();
    return __ldg(((const float4*)feats) + (size_t)idx * C4 + c4);
}

__global__ void pool_z_kernel(const float* __restrict__ feats) {
    int c4   = threadIdx.x;                                    // 0..63
    int pair = blockIdx.x * blockDim.y + threadIdx.y;          // x*D + y
    int voxbase = pair * D;                                    // (x,y,z=0)

    float4 NEG = neg_inf4();
    float4 w0 = NEG, w1 = NEG, w2 = NEG;                       // z = -3..-1
    float4 w3 = load_point(feats, voxbase + 0, c4);
    float4 w4 = load_point(feats, voxbase + 1, c4);
    float4 w5 = load_point(feats, voxbase + 2, c4);

    float4* out = g_bufA + (size_t)voxbase * C4 + c4;
    #pragma unroll 4
    for (int z = 0; z < D; z++) {
        float4 nxt = (z + 3 < D) ? load_point(feats, voxbase + z + 3, c4) : NEG;
        float4 m = vmax4(vmax4(vmax4(w0, w1), vmax4(w2, w3)),
                         vmax4(vmax4(w4, w5), nxt));
        out[(size_t)z * C4] = m;
        w0 = w1; w1 = w2; w2 = w3; w3 = w4; w4 = w5; w5 = nxt;
    }
}

// ---------------------------------------------------------------------------
// 3) y-pass: bufA -> bufB, window along y (stride D*C4 float4)
//    thread = (x,z) pair x c4
// ---------------------------------------------------------------------------
__global__ void pool_y_kernel() {
    int c4   = threadIdx.x;
    int pair = blockIdx.x * blockDim.y + threadIdx.y;          // x*D + z
    int x = pair >> 6, z = pair & 63;

    size_t base   = ((size_t)x * D * D + z) * C4 + c4;         // y = 0
    size_t stride = (size_t)D * C4;

    float4 NEG = neg_inf4();
    float4 w0 = NEG, w1 = NEG, w2 = NEG;
    float4 w3 = g_bufA[base + 0 * stride];
    float4 w4 = g_bufA[base + 1 * stride];
    float4 w5 = g_bufA[base + 2 * stride];

    #pragma unroll 4
    for (int y = 0; y < D; y++) {
        float4 nxt = (y + 3 < D) ? g_bufA[base + (size_t)(y + 3) * stride] : NEG;
        float4 m = vmax4(vmax4(vmax4(w0, w1), vmax4(w2, w3)),
                         vmax4(vmax4(w4, w5), nxt));
        g_bufB[base + (size_t)y * stride] = m;
        w0 = w1; w1 = w2; w2 = w3; w3 = w4; w4 = w5; w5 = nxt;
    }
}

// ---------------------------------------------------------------------------
// 4) x-pass: bufB -> compacted g_y (write only at occupied voxels)
//    thread = (y,z) pair x c4
// ---------------------------------------------------------------------------
__global__ void pool_x_kernel() {
    int c4   = threadIdx.x;
    int pair = blockIdx.x * blockDim.y + threadIdx.y;          // y*D + z
    int y = pair >> 6, z = pair & 63;

    size_t base   = ((size_t)y * D + z) * C4 + c4;             // x = 0
    size_t stride = (size_t)D * D * C4;
    int idxbase   = y * D + z;

    float4 NEG = neg_inf4();
    float4 w0 = NEG, w1 = NEG, w2 = NEG;
    float4 w3 = g_bufB[base + 0 * stride];
    float4 w4 = g_bufB[base + 1 * stride];
    float4 w5 = g_bufB[base + 2 * stride];

    #pragma unroll 4
    for (int x = 0; x < D; x++) {
        float4 nxt = (x + 3 < D) ? g_bufB[base + (size_t)(x + 3) * stride] : NEG;
        int idx = g_idx[x * D * D + idxbase];
        if (idx >= 0) {
            float4 m = vmax4(vmax4(vmax4(w0, w1), vmax4(w2, w3)),
                             vmax4(vmax4(w4, w5), nxt));
            ((float4*)g_y)[(size_t)idx * C4 + c4] = m;
        }
        w0 = w1; w1 = w2; w2 = w3; w3 = w4; w4 = w5; w5 = nxt;
    }
}

// ---------------------------------------------------------------------------
// 5) fused MLP: out = feats * sigmoid(relu(y@W1)@W2)
//    block = 128 rows, 256 threads, 8x8 register tiles, h staged in shared.
// ---------------------------------------------------------------------------
#define BM     128
#define YLD    20       // Ys row pitch (16 + 4 pad)
#define HLD    132      // Hs row pitch (128 + 4 pad)
#define SMEM_FLOATS (BM*YLD + 16*128 + BM*HLD)

__global__ void mlp_kernel(const float* __restrict__ feats,
                           const float* __restrict__ W1,
                           const float* __restrict__ W2,
                           float* __restrict__ out) {
    extern __shared__ float smem[];
    float* Ys = smem;                    // [128][YLD]  y tile (k inner)
    float* Ws = smem + BM * YLD;         // [16][128]   W1/W2 k-tile
    float* Hs = smem + BM * YLD + 16*128; // [128][HLD] hidden (k inner)

    int t  = threadIdx.x;
    int tx = t & 15, ty = t >> 4;
    int row0 = blockIdx.x * BM;

    // ---------- phase 1: h = relu(y @ W1), K=256, N=128 ----------
    float acc[8][8];
    #pragma unroll
    for (int i = 0; i < 8; i++)
        #pragma unroll
        for (int j = 0; j < 8; j++) acc[i][j] = 0.f;

    for (int k0 = 0; k0 < C; k0 += 16) {
        // load y tile [128 rows][16 k]
        #pragma unroll
        for (int u = 0; u < 2; u++) {
            int f = t * 2 + u;               // 0..511 float4 slots
            int m = f >> 2;
            int kk = (f & 3) * 4;
            int gr = row0 + m;
            float4 v = (gr < NPTS)
                ? *(const float4*)(g_y + (size_t)gr * C + k0 + kk)
                : make_float4(0.f, 0.f, 0.f, 0.f);
            *(float4*)(Ys + m * YLD + kk) = v;
        }
        // load W1 tile [16 k][128 n]
        #pragma unroll
        for (int u = 0; u < 2; u++) {
            int f = t * 2 + u;
            int k = f >> 5;
            int n4 = (f & 31) * 4;
            *(float4*)(Ws + k * 128 + n4) =
                *(const float4*)(W1 + (size_t)(k0 + k) * RDIM + n4);
        }
        __syncthreads();

        #pragma unroll
        for (int k = 0; k < 16; k++) {
            float a[8], b[8];
            #pragma unroll
            for (int i = 0; i < 8; i++) a[i] = Ys[(ty*8 + i) * YLD + k];
            float4 b0 = *(const float4*)(Ws + k * 128 + tx * 8);
            float4 b1 = *(const float4*)(Ws + k * 128 + tx * 8 + 4);
            b[0]=b0.x; b[1]=b0.y; b[2]=b0.z; b[3]=b0.w;
            b[4]=b1.x; b[5]=b1.y; b[6]=b1.z; b[7]=b1.w;
            #pragma unroll
            for (int i = 0; i < 8; i++)
                #pragma unroll
                for (int j = 0; j < 8; j++)
                    acc[i][j] = fmaf(a[i], b[j], acc[i][j]);
        }
        __syncthreads();
    }

    // relu -> Hs[row][k]
    #pragma unroll
    for (int i = 0; i < 8; i++) {
        float4 v0 = make_float4(fmaxf(acc[i][0],0.f), fmaxf(acc[i][1],0.f),
                                fmaxf(acc[i][2],0.f), fmaxf(acc[i][3],0.f));
        float4 v1 = make_float4(fmaxf(acc[i][4],0.f), fmaxf(acc[i][5],0.f),
                                fmaxf(acc[i][6],0.f), fmaxf(acc[i][7],0.f));
        *(float4*)(Hs + (ty*8 + i) * HLD + tx*8)     = v0;
        *(float4*)(Hs + (ty*8 + i) * HLD + tx*8 + 4) = v1;
    }
    __syncthreads();

    // ---------- phase 2: o = sigmoid(h @ W2), K=128, N=256 (two halves) ----------
    for (int half = 0; half < 2; half++) {
        int n0 = half * 128;
        float acc2[8][8];
        #pragma unroll
        for (int i = 0; i < 8; i++)
            #pragma unroll
            for (int j = 0; j < 8; j++) acc2[i][j] = 0.f;

        for (int k0 = 0; k0 < RDIM; k0 += 16) {
            #pragma unroll
            for (int u = 0; u < 2; u++) {
                int f = t * 2 + u;
                int k = f >> 5;
                int n4 = (f & 31) * 4;
                *(float4*)(Ws + k * 128 + n4) =
                    *(const float4*)(W2 + (size_t)(k0 + k) * C + n0 + n4);
            }
            __syncthreads();

            #pragma unroll
            for (int k = 0; k < 16; k++) {
                float a[8], b[8];
                #pragma unroll
                for (int i = 0; i < 8; i++) a[i] = Hs[(ty*8 + i) * HLD + k0 + k];
                float4 b0 = *(const float4*)(Ws + k * 128 + tx * 8);
                float4 b1 = *(const float4*)(Ws + k * 128 + tx * 8 + 4);
                b[0]=b0.x; b[1]=b0.y; b[2]=b0.z; b[3]=b0.w;
                b[4]=b1.x; b[5]=b1.y; b[6]=b1.z; b[7]=b1.w;
                #pragma unroll
                for (int i = 0; i < 8; i++)
                    #pragma unroll
                    for (int j = 0; j < 8; j++)
                        acc2[i][j] = fmaf(a[i], b[j], acc2[i][j]);
            }
            __syncthreads();
        }

        // epilogue: out = feats * sigmoid(acc2)
        #pragma unroll
        for (int i = 0; i < 8; i++) {
            int gr = row0 + ty*8 + i;
            if (gr < NPTS) {
                #pragma unroll
                for (int j = 0; j < 8; j += 4) {
                    int gc = n0 + tx*8 + j;
                    float4 fv = *(const float4*)(feats + (size_t)gr * C + gc);
                    float4 o;
                    o.x = fv.x / (1.f + __expf(-acc2[i][j+0]));
                    o.y = fv.y / (1.f + __expf(-acc2[i][j+1]));
                    o.z = fv.z / (1.f + __expf(-acc2[i][j+2]));
                    o.w = fv.w / (1.f + __expf(-acc2[i][j+3]));
                    *(float4*)(out + (size_t)gr * C + gc) = o;
                }
            }
        }
    }
}

// ---------------------------------------------------------------------------
extern "C" void kernel_launch(void* const* d_in, const int* in_sizes, int n_in,
                              void* d_out, int out_size) {
    const float* feats  = (const float*)d_in[0];
    const int*   coords = (const int*)d_in[1];
    const float* W1     = (const float*)d_in[2];
    const float* W2     = (const float*)d_in[3];
    float*       out    = (float*)d_out;

    init_idx_kernel<<<GRID_VOX/256, 256>>>();
    scatter_idx_kernel<<<(NPTS + 255)/256, 256>>>(coords);

    dim3 bt(64, 4);
    pool_z_kernel<<<D*D/4, bt>>>(feats);
    pool_y_kernel<<<D*D/4, bt>>>();
    pool_x_kernel<<<D*D/4, bt>>>();

    int smem_bytes = SMEM_FLOATS * (int)sizeof(float);   // 86 KB
    cudaFuncSetAttribute(mlp_kernel,
                         cudaFuncAttributeMaxDynamicSharedMemorySize, smem_bytes);
    mlp_kernel<<<(NPTS + BM - 1)/BM, 256, smem_bytes>>>(feats, W1, W2, out);
}

// round 5
// speedup vs baseline: 1.1516x; 1.1516x over previous
#include <cuda_runtime.h>
#include <cuda_bf16.h>

#define D     64
#define C     256
#define C4    (C/4)
#define RDIM  128
#define NPTS  100000
#define PAD   3
#define GRID_VOX (D*D*D)

// ---- scratch (device globals; no allocation allowed) ----
__device__ int    g_idx[GRID_VOX];
__device__ float4 g_bufA[(size_t)GRID_VOX * C4];
__device__ float4 g_bufB[(size_t)GRID_VOX * C4];
__device__ float  g_y[(size_t)NPTS * C];

__device__ __forceinline__ float4 vmax4(float4 a, float4 b) {
    return make_float4(fmaxf(a.x, b.x), fmaxf(a.y, b.y),
                       fmaxf(a.z, b.z), fmaxf(a.w, b.w));
}
__device__ __forceinline__ float4 neg_inf4() {
    const float ni = __int_as_float(0xff800000u);
    return make_float4(ni, ni, ni, ni);
}

// ===========================================================================
// Pooling (unchanged — measured near memory roofline)
// ===========================================================================
__global__ void init_idx_kernel() {
    int i = blockIdx.x * blockDim.x + threadIdx.x;
    if (i < GRID_VOX) g_idx[i] = -1;
}
__global__ void scatter_idx_kernel(const int* __restrict__ coords) {
    int n = blockIdx.x * blockDim.x + threadIdx.x;
    if (n < NPTS) {
        int ix = coords[3*n+0], iy = coords[3*n+1], iz = coords[3*n+2];
        g_idx[(ix*D + iy)*D + iz] = n;
    }
}
__device__ __forceinline__ float4 load_point(const float* __restrict__ feats,
                                             int vox, int c4) {
    int idx = g_idx[vox];
    if (idx < 0) return neg_inf4();
    return __ldg(((const float4*)feats) + (size_t)idx * C4 + c4);
}
__global__ void pool_z_kernel(const float* __restrict__ feats) {
    int c4   = threadIdx.x;
    int pair = blockIdx.x * blockDim.y + threadIdx.y;
    int voxbase = pair * D;
    float4 NEG = neg_inf4();
    float4 w0 = NEG, w1 = NEG, w2 = NEG;
    float4 w3 = load_point(feats, voxbase + 0, c4);
    float4 w4 = load_point(feats, voxbase + 1, c4);
    float4 w5 = load_point(feats, voxbase + 2, c4);
    float4* out = g_bufA + (size_t)voxbase * C4 + c4;
    #pragma unroll 4
    for (int z = 0; z < D; z++) {
        float4 nxt = (z + 3 < D) ? load_point(feats, voxbase + z + 3, c4) : NEG;
        float4 m = vmax4(vmax4(vmax4(w0, w1), vmax4(w2, w3)),
                         vmax4(vmax4(w4, w5), nxt));
        out[(size_t)z * C4] = m;
        w0 = w1; w1 = w2; w2 = w3; w3 = w4; w4 = w5; w5 = nxt;
    }
}
__global__ void pool_y_kernel() {
    int c4   = threadIdx.x;
    int pair = blockIdx.x * blockDim.y + threadIdx.y;
    int x = pair >> 6, z = pair & 63;
    size_t base   = ((size_t)x * D * D + z) * C4 + c4;
    size_t stride = (size_t)D * C4;
    float4 NEG = neg_inf4();
    float4 w0 = NEG, w1 = NEG, w2 = NEG;
    float4 w3 = g_bufA[base + 0 * stride];
    float4 w4 = g_bufA[base + 1 * stride];
    float4 w5 = g_bufA[base + 2 * stride];
    #pragma unroll 4
    for (int y = 0; y < D; y++) {
        float4 nxt = (y + 3 < D) ? g_bufA[base + (size_t)(y + 3) * stride] : NEG;
        float4 m = vmax4(vmax4(vmax4(w0, w1), vmax4(w2, w3)),
                         vmax4(vmax4(w4, w5), nxt));
        g_bufB[base + (size_t)y * stride] = m;
        w0 = w1; w1 = w2; w2 = w3; w3 = w4; w4 = w5; w5 = nxt;
    }
}
__global__ void pool_x_kernel() {
    int c4   = threadIdx.x;
    int pair = blockIdx.x * blockDim.y + threadIdx.y;
    int y = pair >> 6, z = pair & 63;
    size_t base   = ((size_t)y * D + z) * C4 + c4;
    size_t stride = (size_t)D * D * C4;
    int idxbase   = y * D + z;
    float4 NEG = neg_inf4();
    float4 w0 = NEG, w1 = NEG, w2 = NEG;
    float4 w3 = g_bufB[base + 0 * stride];
    float4 w4 = g_bufB[base + 1 * stride];
    float4 w5 = g_bufB[base + 2 * stride];
    #pragma unroll 4
    for (int x = 0; x < D; x++) {
        float4 nxt = (x + 3 < D) ? g_bufB[base + (size_t)(x + 3) * stride] : NEG;
        int idx = g_idx[x * D * D + idxbase];
        if (idx >= 0) {
            float4 m = vmax4(vmax4(vmax4(w0, w1), vmax4(w2, w3)),
                             vmax4(vmax4(w4, w5), nxt));
            ((float4*)g_y)[(size_t)idx * C4 + c4] = m;
        }
        w0 = w1; w1 = w2; w2 = w3; w3 = w4; w4 = w5; w5 = nxt;
    }
}

// ===========================================================================
// MLP via legacy mma.sync tf32 (m16n8k8) — compiles for plain sm_103
// ===========================================================================
__device__ __forceinline__ unsigned f2tf32(float f) {
    unsigned r; asm("cvt.rna.tf32.f32 %0, %1;" : "=r"(r) : "f"(f)); return r;
}
__device__ __forceinline__ void mma8(float* c, const unsigned* a,
                                     unsigned b0, unsigned b1) {
    asm("mma.sync.aligned.m16n8k8.row.col.f32.tf32.tf32.f32 "
        "{%0,%1,%2,%3}, {%4,%5,%6,%7}, {%8,%9}, {%0,%1,%2,%3};"
        : "+f"(c[0]), "+f"(c[1]), "+f"(c[2]), "+f"(c[3])
        : "r"(a[0]), "r"(a[1]), "r"(a[2]), "r"(a[3]), "r"(b0), "r"(b1));
}

// SMEM layout (float units):
//   XS0 @ 0      (128 x 36)
//   XS1 @ 4608
//   WS0 @ 9216   (128 x 36, B operand tiles [n][k])
//   WS1 @ 13824
//   HS  @ 18432  (128 x 132, hidden as tf32 bits)
#define OFF_XS0 0
#define OFF_XS1 4608
#define OFF_WS0 9216
#define OFF_WS1 13824
#define OFF_HS  18432
#define MLP_SMEM ((18432 + 128*132) * 4)   // 141312 bytes

// One 32-wide K chunk of mma work for a 128x128 output tile.
// As: [row][k], stride astride, k window at kbase..kbase+31 (conflict-free:
// astride mod 32 == 4). Bs: [n][k] stride 36.
__device__ __forceinline__ void compute_chunk(const unsigned* __restrict__ As,
                                              int astride, int kbase,
                                              const unsigned* __restrict__ Bs,
                                              int wm, int wn, int lane,
                                              float acc[2][8][4]) {
    int g = lane >> 2, tg = lane & 3;
    #pragma unroll
    for (int ks = 0; ks < 4; ks++) {
        int k = kbase + ks * 8 + tg;
        unsigned a[2][4];
        #pragma unroll
        for (int mt = 0; mt < 2; mt++) {
            int r = wm * 32 + mt * 16 + g;
            a[mt][0] = As[r * astride + k];
            a[mt][1] = As[(r + 8) * astride + k];
            a[mt][2] = As[r * astride + k + 4];
            a[mt][3] = As[(r + 8) * astride + k + 4];
        }
        #pragma unroll
        for (int nt = 0; nt < 8; nt++) {
            int n = wn * 64 + nt * 8 + g;
            unsigned b0 = Bs[n * 36 + ks * 8 + tg];
            unsigned b1 = Bs[n * 36 + ks * 8 + tg + 4];
            mma8(acc[0][nt], a[0], b0, b1);
            mma8(acc[1][nt], a[1], b0, b1);
        }
    }
}

// ---- staging: global -> regs -> (cvt tf32) -> smem ----
__device__ __forceinline__ void ldg_X(float4 v[4], int tid, int row0, int kt) {
    #pragma unroll
    for (int u = 0; u < 4; u++) {
        int id = tid + u * 256;          // 1024 float4 = 128 rows x 8
        int r = id >> 3, c4 = id & 7;
        v[u] = make_float4(0.f, 0.f, 0.f, 0.f);
        if (row0 + r < NPTS)
            v[u] = *(const float4*)(g_y + (size_t)(row0 + r) * C + kt * 32 + c4 * 4);
    }
}
__device__ __forceinline__ void sts_X(unsigned* Xs, int tid, const float4 v[4]) {
    #pragma unroll
    for (int u = 0; u < 4; u++) {
        int id = tid + u * 256;
        int r = id >> 3, c4 = id & 7;
        uint4 w = make_uint4(f2tf32(v[u].x), f2tf32(v[u].y),
                             f2tf32(v[u].z), f2tf32(v[u].w));
        *(uint4*)(Xs + r * 36 + c4 * 4) = w;
    }
}
__device__ __forceinline__ void ldg_W(float4 v[4], int tid,
                                      const float* __restrict__ W, int ldw,
                                      int kt, int ncol0) {
    #pragma unroll
    for (int u = 0; u < 4; u++) {
        int e = tid + u * 256;           // 1024 float4 = 32 k x 32 n4
        int k = e >> 5, n4 = e & 31;
        v[u] = *(const float4*)(W + (size_t)(kt * 32 + k) * ldw + ncol0 + n4 * 4);
    }
}
__device__ __forceinline__ void sts_W(unsigned* Ws, int tid, const float4 v[4]) {
    #pragma unroll
    for (int u = 0; u < 4; u++) {
        int e = tid + u * 256;
        int k = e >> 5, n4 = e & 31;
        Ws[(n4 * 4 + 0) * 36 + k] = f2tf32(v[u].x);
        Ws[(n4 * 4 + 1) * 36 + k] = f2tf32(v[u].y);
        Ws[(n4 * 4 + 2) * 36 + k] = f2tf32(v[u].z);
        Ws[(n4 * 4 + 3) * 36 + k] = f2tf32(v[u].w);
    }
}

__global__ void __launch_bounds__(256, 1)
mlp_mma_kernel(const float* __restrict__ feats,
               const float* __restrict__ W1,
               const float* __restrict__ W2,
               float* __restrict__ out) {
    extern __shared__ float smf[];
    unsigned* XS0 = (unsigned*)(smf + OFF_XS0);
    unsigned* XS1 = (unsigned*)(smf + OFF_XS1);
    unsigned* WS0 = (unsigned*)(smf + OFF_WS0);
    unsigned* WS1 = (unsigned*)(smf + OFF_WS1);
    unsigned* HS  = (unsigned*)(smf + OFF_HS);
    unsigned* XSb[2] = {XS0, XS1};
    unsigned* WSb[2] = {WS0, WS1};

    int tid  = threadIdx.x;
    int lane = tid & 31, wid = tid >> 5;
    int wm = wid >> 1, wn = wid & 1;
    int g = lane >> 2, tg = lane & 3;
    int row0 = blockIdx.x * 128;

    float4 vx[4], vw[4];
    float acc[2][8][4];

    // ---------------- GEMM1: H = relu(Y @ W1), K=256 in 8 chunks ------------
    #pragma unroll
    for (int mt = 0; mt < 2; mt++)
        #pragma unroll
        for (int nt = 0; nt < 8; nt++)
            #pragma unroll
            for (int q = 0; q < 4; q++) acc[mt][nt][q] = 0.f;

    ldg_X(vx, tid, row0, 0);
    ldg_W(vw, tid, W1, RDIM, 0, 0);
    sts_X(XS0, tid, vx);
    sts_W(WS0, tid, vw);
    __syncthreads();

    for (int kt = 0; kt < 8; kt++) {
        if (kt < 7) {
            ldg_X(vx, tid, row0, kt + 1);
            ldg_W(vw, tid, W1, RDIM, kt + 1, 0);
        }
        compute_chunk(XSb[kt & 1], 36, 0, WSb[kt & 1], wm, wn, lane, acc);
        if (kt < 7) {
            sts_X(XSb[(kt + 1) & 1], tid, vx);
            sts_W(WSb[(kt + 1) & 1], tid, vw);
        }
        __syncthreads();
    }

    // relu + tf32 -> HS[row][k] (stride 132)
    #pragma unroll
    for (int mt = 0; mt < 2; mt++) {
        #pragma unroll
        for (int nt = 0; nt < 8; nt++) {
            int rr = wm * 32 + mt * 16 + g;
            int cc = wn * 64 + nt * 8 + 2 * tg;
            uint2 w0 = make_uint2(f2tf32(fmaxf(acc[mt][nt][0], 0.f)),
                                  f2tf32(fmaxf(acc[mt][nt][1], 0.f)));
            uint2 w1 = make_uint2(f2tf32(fmaxf(acc[mt][nt][2], 0.f)),
                                  f2tf32(fmaxf(acc[mt][nt][3], 0.f)));
            *(uint2*)(HS + rr * 132 + cc)       = w0;
            *(uint2*)(HS + (rr + 8) * 132 + cc) = w1;
        }
    }
    __syncthreads();

    // ------------- GEMM2: O = H @ W2 (K=128), two 128-col halves ------------
    for (int half = 0; half < 2; half++) {
        #pragma unroll
        for (int mt = 0; mt < 2; mt++)
            #pragma unroll
            for (int nt = 0; nt < 8; nt++)
                #pragma unroll
                for (int q = 0; q < 4; q++) acc[mt][nt][q] = 0.f;

        ldg_W(vw, tid, W2, C, 0, half * 128);
        sts_W(WS0, tid, vw);
        __syncthreads();

        for (int kc = 0; kc < 4; kc++) {
            if (kc < 3) ldg_W(vw, tid, W2, C, kc + 1, half * 128);
            compute_chunk(HS, 132, kc * 32, WSb[kc & 1], wm, wn, lane, acc);
            if (kc < 3) sts_W(WSb[(kc + 1) & 1], tid, vw);
            __syncthreads();
        }

        // epilogue: out = feats * sigmoid(acc)
        #pragma unroll
        for (int mt = 0; mt < 2; mt++) {
            #pragma unroll
            for (int nt = 0; nt < 8; nt++) {
                int rr = wm * 32 + mt * 16 + g;
                int cc = half * 128 + wn * 64 + nt * 8 + 2 * tg;
                #pragma unroll
                for (int h = 0; h < 2; h++) {
                    int row = row0 + rr + h * 8;
                    if (row < NPTS) {
                        float z0 = acc[mt][nt][h * 2 + 0];
                        float z1 = acc[mt][nt][h * 2 + 1];
                        float2 fv = *(const float2*)(feats + (size_t)row * C + cc);
                        float2 o;
                        o.x = fv.x / (1.f + __expf(-z0));
                        o.y = fv.y / (1.f + __expf(-z1));
                        *(float2*)(out + (size_t)row * C + cc) = o;
                    }
                }
            }
        }
    }
}

// ===========================================================================
extern "C" void kernel_launch(void* const* d_in, const int* in_sizes, int n_in,
                              void* d_out, int out_size) {
    const float* feats  = (const float*)d_in[0];
    const int*   coords = (const int*)d_in[1];
    const float* W1     = (const float*)d_in[2];
    const float* W2     = (const float*)d_in[3];
    float*       out    = (float*)d_out;

    init_idx_kernel<<<GRID_VOX/256, 256>>>();
    scatter_idx_kernel<<<(NPTS + 255)/256, 256>>>(coords);

    dim3 bt(64, 4);
    pool_z_kernel<<<D*D/4, bt>>>(feats);
    pool_y_kernel<<<D*D/4, bt>>>();
    pool_x_kernel<<<D*D/4, bt>>>();

    cudaFuncSetAttribute(mlp_mma_kernel,
                         cudaFuncAttributeMaxDynamicSharedMemorySize, MLP_SMEM);
    mlp_mma_kernel<<<(NPTS + 127)/128, 256, MLP_SMEM>>>(feats, W1, W2, out);
}

// round 6
// speedup vs baseline: 1.2495x; 1.0850x over previous
#include <cuda_runtime.h>
#include <cuda_bf16.h>

#define D     64
#define C     256
#define C4    (C/4)
#define RDIM  128
#define NPTS  100000
#define PAD   3
#define GRID_VOX (D*D*D)

// ---- scratch (device globals; no allocation allowed) ----
__device__ int    g_idx[GRID_VOX];                   // vox=(x*64+y)*64+z -> point
__device__ int    g_idxT[GRID_VOX];                  // (z*64+x)*64+y -> point
__device__ float4 g_bufA[(size_t)GRID_VOX * C4];     // z-pooled dense grid
__device__ float  g_y[(size_t)NPTS * C];             // fully pooled, compacted

__device__ __forceinline__ float4 vmax4(float4 a, float4 b) {
    return make_float4(fmaxf(a.x, b.x), fmaxf(a.y, b.y),
                       fmaxf(a.z, b.z), fmaxf(a.w, b.w));
}
__device__ __forceinline__ float4 neg_inf4() {
    const float ni = __int_as_float(0xff800000u);
    return make_float4(ni, ni, ni, ni);
}

// ===========================================================================
// init + scatter
// ===========================================================================
__global__ void init_idx_kernel() {
    int i = blockIdx.x * blockDim.x + threadIdx.x;
    if (i < GRID_VOX) { g_idx[i] = -1; g_idxT[i] = -1; }
}
__global__ void scatter_idx_kernel(const int* __restrict__ coords) {
    int n = blockIdx.x * blockDim.x + threadIdx.x;
    if (n < NPTS) {
        int ix = coords[3*n+0], iy = coords[3*n+1], iz = coords[3*n+2];
        g_idx[(ix*D + iy)*D + iz] = n;
        g_idxT[(iz*D + ix)*D + iy] = n;
    }
}

// ===========================================================================
// z-pass (unchanged — near memory roofline)
// ===========================================================================
__device__ __forceinline__ float4 load_point(const float* __restrict__ feats,
                                             int vox, int c4) {
    int idx = g_idx[vox];
    if (idx < 0) return neg_inf4();
    return __ldg(((const float4*)feats) + (size_t)idx * C4 + c4);
}
__global__ void pool_z_kernel(const float* __restrict__ feats) {
    int c4   = threadIdx.x;
    int pair = blockIdx.x * blockDim.y + threadIdx.y;   // x*D + y
    int voxbase = pair * D;
    float4 NEG = neg_inf4();
    float4 w0 = NEG, w1 = NEG, w2 = NEG;
    float4 w3 = load_point(feats, voxbase + 0, c4);
    float4 w4 = load_point(feats, voxbase + 1, c4);
    float4 w5 = load_point(feats, voxbase + 2, c4);
    float4* out = g_bufA + (size_t)voxbase * C4 + c4;
    #pragma unroll 4
    for (int z = 0; z < D; z++) {
        float4 nxt = (z + 3 < D) ? load_point(feats, voxbase + z + 3, c4) : NEG;
        float4 m = vmax4(vmax4(vmax4(w0, w1), vmax4(w2, w3)),
                         vmax4(vmax4(w4, w5), nxt));
        out[(size_t)z * C4] = m;
        w0 = w1; w1 = w2; w2 = w3; w3 = w4; w4 = w5; w5 = nxt;
    }
}

// ===========================================================================
// fused y+x pass: bufA -> g_y (compacted)
// block = (z, c4 group of 4, y-tile of 16); smem tile 64x * 22y * 4c4 float4
// ===========================================================================
#define YT        16
#define YH        (YT + 6)                 // 22 rows incl. halo
#define INS_F4    (YH * 65 * 4)            // padded x-stride 65
#define POOL_SMEM (INS_F4 * 16 + 1024 * 4) // 95616 bytes

__global__ void __launch_bounds__(256, 2)
pool_yx_kernel() {
    extern __shared__ float4 in_s[];
    int* idx_s = (int*)(in_s + INS_F4);

    int bid = blockIdx.x;
    int z   = bid & 63;
    int c4g = (bid >> 6) & 15;
    int y0  = (bid >> 10) * YT;
    int tid = threadIdx.x;

    float4 NEG = neg_inf4();

    // load tile: 64x * 22y * 4c4, 64B-contiguous global chunks
    for (int i = tid; i < 64 * YH * 4; i += 256) {
        int c4 = i & 3, x = (i >> 2) & 63, yt = i >> 8;
        int ygl = y0 + yt - 3;
        float4 v = NEG;
        if (ygl >= 0 && ygl < 64)
            v = g_bufA[((size_t)((x * 64 + ygl) * 64 + z)) * C4 + c4g * 4 + c4];
        in_s[(yt * 65 + x) * 4 + c4] = v;
    }
    // idx tile: [64x][16y]
    for (int i = tid; i < 1024; i += 256) {
        int x = i >> 4, yy = i & 15;
        idx_s[x * 16 + yy] = g_idxT[(z * 64 + x) * 64 + y0 + yy];
    }
    __syncthreads();

    int c4 = tid & 3;
    int y  = (tid >> 2) & 15;
    int xq = tid >> 6;
    int x0 = xq * 16;

    // y-window max at column x (tile rows y..y+6)
    auto ycol = [&](int x) -> float4 {
        const float4* p = in_s + (y * 65 + x) * 4 + c4;
        float4 m = p[0];
        #pragma unroll
        for (int j = 1; j < 7; j++) m = vmax4(m, p[j * 65 * 4]);
        return m;
    };

    float4 w0, w1, w2, w3, w4, w5;
    w0 = (x0 - 3 >= 0) ? ycol(x0 - 3) : NEG;
    w1 = (x0 - 2 >= 0) ? ycol(x0 - 2) : NEG;
    w2 = (x0 - 1 >= 0) ? ycol(x0 - 1) : NEG;
    w3 = ycol(x0 + 0);
    w4 = ycol(x0 + 1);
    w5 = ycol(x0 + 2);

    #pragma unroll 4
    for (int xx = x0; xx < x0 + 16; xx++) {
        float4 nxt = (xx + 3 < 64) ? ycol(xx + 3) : NEG;
        int id = idx_s[xx * 16 + y];
        if (id >= 0) {
            float4 m = vmax4(vmax4(vmax4(w0, w1), vmax4(w2, w3)),
                             vmax4(vmax4(w4, w5), nxt));
            ((float4*)g_y)[(size_t)id * C4 + c4g * 4 + c4] = m;
        }
        w0 = w1; w1 = w2; w2 = w3; w3 = w4; w4 = w5; w5 = nxt;
    }
}

// ===========================================================================
// MLP via mma.sync tf32 m16n8k8, fragment-major SMEM, 96KB -> 2 CTAs/SM
// ===========================================================================
__device__ __forceinline__ unsigned f2tf32(float f) {
    unsigned r; asm("cvt.rna.tf32.f32 %0, %1;" : "=r"(r) : "f"(f)); return r;
}
__device__ __forceinline__ void mma8(float* c, const unsigned* a,
                                     unsigned b0, unsigned b1) {
    asm("mma.sync.aligned.m16n8k8.row.col.f32.tf32.tf32.f32 "
        "{%0,%1,%2,%3}, {%4,%5,%6,%7}, {%8,%9}, {%0,%1,%2,%3};"
        : "+f"(c[0]), "+f"(c[1]), "+f"(c[2]), "+f"(c[3])
        : "r"(a[0]), "r"(a[1]), "r"(a[2]), "r"(a[3]), "r"(b0), "r"(b1));
}

// byte offsets in dynamic smem
#define OFF_XS0 0        // 16KB  (A-frag tile, GEMM1)        } aliased by HS
#define OFF_XS1 16384    // 16KB                              } (4 chunks x 16KB,
#define OFF_WS0 32768    // 16KB  (B-frag tile, GEMM1)        }  A-frag layout)
#define OFF_WS1 49152    // 16KB                              }
#define OFF_HS  0
#define OFF_C0  65536    // 16KB  (B-frag tile, GEMM2)
#define OFF_C1  81920    // 16KB
#define MLP_SMEM 98304

// A-frag tile (one 32-k chunk, 128 rows): uint4 slot (mb*4+ks)*32 + lane
//   = {A[mb16+g][k], A[mb16+8+g][k], A[mb16+g][k+4], A[mb16+8+g][k+4]}, k=ks*8+tg
// B-frag tile (one 32-k chunk, 128 n): uint2 slot (nb*4+ks)*32 + lane
//   = {B[nb8+g][k], B[nb8+g][k+4]}

__device__ __forceinline__ void compute_chunk(const uint4* __restrict__ A4,
                                              const uint2* __restrict__ B2,
                                              int wm, int wn, int lane,
                                              float acc[2][8][4]) {
    #pragma unroll
    for (int ks = 0; ks < 4; ks++) {
        uint4 a0 = A4[((wm * 2 + 0) * 4 + ks) * 32 + lane];
        uint4 a1 = A4[((wm * 2 + 1) * 4 + ks) * 32 + lane];
        unsigned ar0[4] = {a0.x, a0.y, a0.z, a0.w};
        unsigned ar1[4] = {a1.x, a1.y, a1.z, a1.w};
        #pragma unroll
        for (int nt = 0; nt < 8; nt++) {
            uint2 b = B2[((wn * 8 + nt) * 4 + ks) * 32 + lane];
            mma8(acc[0][nt], ar0, b.x, b.y);
            mma8(acc[1][nt], ar1, b.x, b.y);
        }
    }
}

__device__ __forceinline__ void ldg_X(float4 v[4], int tid, int row0, int kt) {
    #pragma unroll
    for (int u = 0; u < 4; u++) {
        int id = tid + u * 256;
        int r = id >> 3, c4 = id & 7;
        v[u] = make_float4(0.f, 0.f, 0.f, 0.f);
        if (row0 + r < NPTS)
            v[u] = *(const float4*)(g_y + (size_t)(row0 + r) * C + kt * 32 + c4 * 4);
    }
}
__device__ __forceinline__ void sts_X(unsigned* X32, int tid, const float4 v[4]) {
    #pragma unroll
    for (int u = 0; u < 4; u++) {
        int id = tid + u * 256;
        int r = id >> 3, c4 = id & 7;
        int mb = r >> 4, g = r & 7, rb = (r >> 3) & 1;
        int ks = c4 >> 1, kh = c4 & 1;
        int s0 = (mb * 4 + ks) * 32 + g * 4;
        int comp = rb + 2 * kh;
        float vv[4] = {v[u].x, v[u].y, v[u].z, v[u].w};
        #pragma unroll
        for (int j = 0; j < 4; j++)
            X32[(s0 + j) * 4 + comp] = f2tf32(vv[j]);
    }
}
__device__ __forceinline__ void ldg_W(float4 v[4], int tid,
                                      const float* __restrict__ W, int ldw,
                                      int kt, int ncol0) {
    #pragma unroll
    for (int u = 0; u < 4; u++) {
        int e = tid + u * 256;
        int k = e >> 5, n4 = e & 31;
        v[u] = *(const float4*)(W + (size_t)(kt * 32 + k) * ldw + ncol0 + n4 * 4);
    }
}
__device__ __forceinline__ void sts_W(unsigned* W32, int tid, const float4 v[4]) {
    #pragma unroll
    for (int u = 0; u < 4; u++) {
        int e = tid + u * 256;
        int kk = e >> 5, n4 = e & 31;
        int ks = kk >> 3, k8 = kk & 7;
        int tg = k8 & 3, kh = k8 >> 2;
        float vv[4] = {v[u].x, v[u].y, v[u].z, v[u].w};
        #pragma unroll
        for (int i = 0; i < 4; i++) {
            int n = n4 * 4 + i;
            int s = ((n >> 3) * 4 + ks) * 32 + (n & 7) * 4 + tg;
            W32[s * 2 + kh] = f2tf32(vv[i]);
        }
    }
}

__global__ void __launch_bounds__(256, 2)
mlp_mma_kernel(const float* __restrict__ feats,
               const float* __restrict__ W1,
               const float* __restrict__ W2,
               float* __restrict__ out) {
    extern __shared__ char smb[];
    unsigned* X32b[2] = {(unsigned*)(smb + OFF_XS0), (unsigned*)(smb + OFF_XS1)};
    unsigned* W32b[2] = {(unsigned*)(smb + OFF_WS0), (unsigned*)(smb + OFF_WS1)};
    unsigned* C32b[2] = {(unsigned*)(smb + OFF_C0),  (unsigned*)(smb + OFF_C1)};
    unsigned* HS32    = (unsigned*)(smb + OFF_HS);

    int tid  = threadIdx.x;
    int lane = tid & 31, wid = tid >> 5;
    int wm = wid >> 1, wn = wid & 1;
    int g = lane >> 2, tg = lane & 3;
    int row0 = blockIdx.x * 128;

    float4 vx[4], vw[4];
    float acc[2][8][4];

    // ---------------- GEMM1: H = relu(Y @ W1), K=256, 8 chunks --------------
    #pragma unroll
    for (int mt = 0; mt < 2; mt++)
        #pragma unroll
        for (int nt = 0; nt < 8; nt++)
            #pragma unroll
            for (int q = 0; q < 4; q++) acc[mt][nt][q] = 0.f;

    ldg_X(vx, tid, row0, 0);
    ldg_W(vw, tid, W1, RDIM, 0, 0);
    sts_X(X32b[0], tid, vx);
    sts_W(W32b[0], tid, vw);
    __syncthreads();

    for (int kt = 0; kt < 8; kt++) {
        if (kt < 7) {
            ldg_X(vx, tid, row0, kt + 1);
            ldg_W(vw, tid, W1, RDIM, kt + 1, 0);
        }
        compute_chunk((const uint4*)X32b[kt & 1], (const uint2*)W32b[kt & 1],
                      wm, wn, lane, acc);
        if (kt < 7) {
            sts_X(X32b[(kt + 1) & 1], tid, vx);
            sts_W(W32b[(kt + 1) & 1], tid, vw);
        }
        __syncthreads();
    }

    // relu + tf32 -> HS in A-frag layout (aliases XS/WS; all reads done)
    #pragma unroll
    for (int mt = 0; mt < 2; mt++) {
        #pragma unroll
        for (int nt = 0; nt < 8; nt++) {
            int mb = wm * 2 + mt;
            int ks = nt & 3;
            int ch = wn * 2 + (nt >> 2);
            unsigned* H = HS32 + ch * 4096;
            #pragma unroll
            for (int q = 0; q < 4; q++) {
                int rb = q >> 1, kadd = q & 1;
                int k8 = 2 * tg + kadd;
                int tgd = k8 & 3, kh = k8 >> 2;
                int s = (mb * 4 + ks) * 32 + g * 4 + tgd;
                H[s * 4 + rb + 2 * kh] = f2tf32(fmaxf(acc[mt][nt][q], 0.f));
            }
        }
    }
    __syncthreads();

    // ------------- GEMM2: O = H @ W2 (K=128), two 128-col halves ------------
    for (int half = 0; half < 2; half++) {
        #pragma unroll
        for (int mt = 0; mt < 2; mt++)
            #pragma unroll
            for (int nt = 0; nt < 8; nt++)
                #pragma unroll
                for (int q = 0; q < 4; q++) acc[mt][nt][q] = 0.f;

        ldg_W(vw, tid, W2, C, 0, half * 128);
        sts_W(C32b[0], tid, vw);
        __syncthreads();

        for (int kc = 0; kc < 4; kc++) {
            if (kc < 3) ldg_W(vw, tid, W2, C, kc + 1, half * 128);
            compute_chunk((const uint4*)(HS32 + kc * 4096),
                          (const uint2*)C32b[kc & 1], wm, wn, lane, acc);
            if (kc < 3) sts_W(C32b[(kc + 1) & 1], tid, vw);
            __syncthreads();
        }

        // epilogue: out = feats * sigmoid(acc)
        #pragma unroll
        for (int mt = 0; mt < 2; mt++) {
            #pragma unroll
            for (int nt = 0; nt < 8; nt++) {
                int rr = wm * 32 + mt * 16 + g;
                int cc = half * 128 + wn * 64 + nt * 8 + 2 * tg;
                #pragma unroll
                for (int h = 0; h < 2; h++) {
                    int row = row0 + rr + h * 8;
                    if (row < NPTS) {
                        float z0 = acc[mt][nt][h * 2 + 0];
                        float z1 = acc[mt][nt][h * 2 + 1];
                        float2 fv = *(const float2*)(feats + (size_t)row * C + cc);
                        float2 o;
                        o.x = fv.x / (1.f + __expf(-z0));
                        o.y = fv.y / (1.f + __expf(-z1));
                        *(float2*)(out + (size_t)row * C + cc) = o;
                    }
                }
            }
        }
    }
}

// ===========================================================================
extern "C" void kernel_launch(void* const* d_in, const int* in_sizes, int n_in,
                              void* d_out, int out_size) {
    const float* feats  = (const float*)d_in[0];
    const int*   coords = (const int*)d_in[1];
    const float* W1     = (const float*)d_in[2];
    const float* W2     = (const float*)d_in[3];
    float*       out    = (float*)d_out;

    init_idx_kernel<<<GRID_VOX/256, 256>>>();
    scatter_idx_kernel<<<(NPTS + 255)/256, 256>>>(coords);

    dim3 bt(64, 4);
    pool_z_kernel<<<D*D/4, bt>>>(feats);

    cudaFuncSetAttribute(pool_yx_kernel,
                         cudaFuncAttributeMaxDynamicSharedMemorySize, POOL_SMEM);
    pool_yx_kernel<<<64 * 16 * 4, 256, POOL_SMEM>>>();

    cudaFuncSetAttribute(mlp_mma_kernel,
                         cudaFuncAttributeMaxDynamicSharedMemorySize, MLP_SMEM);
    mlp_mma_kernel<<<(NPTS + 127)/128, 256, MLP_SMEM>>>(feats, W1, W2, out);
}

// round 7
// speedup vs baseline: 1.6701x; 1.3366x over previous
#include <cuda_runtime.h>
#include <cuda_bf16.h>
#include <cuda_fp16.h>

#define D     64
#define C     256
#define RDIM  128
#define NPTS  100000
#define GRID_VOX (D*D*D)

// ---- scratch (device globals; no allocation allowed) ----
__device__ int   g_idx[GRID_VOX];                 // (x*64+y)*64+z -> point
__device__ int   g_idxT[GRID_VOX];                // (z*64+x)*64+y -> point
__device__ uint4 g_bufA_h[(size_t)GRID_VOX * 32]; // z-pooled grid, fp16 (134MB)
__device__ uint4 g_y4[(size_t)NPTS * 32];         // pooled, compacted, fp16 (51MB)

#define NEGH 0xFC00FC00u
__device__ __forceinline__ uint4 negh4() { return make_uint4(NEGH, NEGH, NEGH, NEGH); }

__device__ __forceinline__ unsigned h2max(unsigned a, unsigned b) {
    __half2 r = __hmax2(*reinterpret_cast<__half2*>(&a),
                        *reinterpret_cast<__half2*>(&b));
    return *reinterpret_cast<unsigned*>(&r);
}
__device__ __forceinline__ uint4 hmax4(uint4 a, uint4 b) {
    return make_uint4(h2max(a.x, b.x), h2max(a.y, b.y),
                      h2max(a.z, b.z), h2max(a.w, b.w));
}
__device__ __forceinline__ unsigned pack2(float a, float b) {
    __half2 h = __floats2half2_rn(a, b);
    return *reinterpret_cast<unsigned*>(&h);
}

// ===========================================================================
// init + scatter
// ===========================================================================
__global__ void init_idx_kernel() {
    int i = blockIdx.x * blockDim.x + threadIdx.x;
    if (i < GRID_VOX) { g_idx[i] = -1; g_idxT[i] = -1; }
}
__global__ void scatter_idx_kernel(const int* __restrict__ coords) {
    int n = blockIdx.x * blockDim.x + threadIdx.x;
    if (n < NPTS) {
        int ix = coords[3*n+0], iy = coords[3*n+1], iz = coords[3*n+2];
        g_idx[(ix*D + iy)*D + iz] = n;
        g_idxT[(iz*D + ix)*D + iy] = n;
    }
}

// ===========================================================================
// z-pass: gather feats (fp32) -> fp16, sliding window-7 along z -> bufA (fp16)
// blockDim (32, 8): thread = (c2 unit of 8 ch, (x,y) pair)
// ===========================================================================
__device__ __forceinline__ uint4 load_point_h(const float* __restrict__ feats,
                                              int vox, int c2) {
    int idx = g_idx[vox];
    if (idx < 0) return negh4();
    const float4* p = (const float4*)(feats + (size_t)idx * C + c2 * 8);
    float4 f0 = __ldg(p), f1 = __ldg(p + 1);
    return make_uint4(pack2(f0.x, f0.y), pack2(f0.z, f0.w),
                      pack2(f1.x, f1.y), pack2(f1.z, f1.w));
}
__global__ void pool_z_kernel(const float* __restrict__ feats) {
    int c2   = threadIdx.x;                              // 0..31
    int pair = blockIdx.x * blockDim.y + threadIdx.y;    // x*64+y
    int voxbase = pair * D;
    uint4 NEG = negh4();
    uint4 w0 = NEG, w1 = NEG, w2 = NEG;
    uint4 w3 = load_point_h(feats, voxbase + 0, c2);
    uint4 w4 = load_point_h(feats, voxbase + 1, c2);
    uint4 w5 = load_point_h(feats, voxbase + 2, c2);
    uint4* out = g_bufA_h + (size_t)voxbase * 32 + c2;
    #pragma unroll 4
    for (int z = 0; z < D; z++) {
        uint4 nxt = (z + 3 < D) ? load_point_h(feats, voxbase + z + 3, c2) : NEG;
        uint4 m = hmax4(hmax4(hmax4(w0, w1), hmax4(w2, w3)),
                        hmax4(hmax4(w4, w5), nxt));
        out[(size_t)z * 32] = m;
        w0 = w1; w1 = w2; w2 = w3; w3 = w4; w4 = w5; w5 = nxt;
    }
}

// ===========================================================================
// fused y+x pass, two-phase: bufA(fp16) -> g_y4 (compacted fp16)
// block = (z, cg group of 32 ch, y-tile of 16). grid = 64*8*4 = 2048
// phase A: per-thread (x,cq) register-sliding y-window -> ym smem
// phase B: per-thread (xq,y,cq) register-sliding x-window over ym
// ===========================================================================
#define POOL_SMEM (64*65*16 + 4096)    // 70656 bytes

__global__ void __launch_bounds__(256, 2)
pool_yx_kernel() {
    extern __shared__ uint4 ym[];                 // [x:64][stride 65: y*4+cq]
    int* idx_s = (int*)(ym + 64 * 65);            // [64x][16y]

    int bid = blockIdx.x;
    int z   = bid & 63;
    int cg  = (bid >> 6) & 7;
    int y0  = (bid >> 9) * 16;
    int tid = threadIdx.x;
    uint4 NEG = negh4();

    // ---- phase A: y-window max, sliding in registers ----
    {
        int x = tid >> 2, cq = tid & 3;
        const uint4* src = g_bufA_h + ((size_t)(x * 64) * 64 + z) * 32 + cg * 4 + cq;
        uint4 w0, w1, w2, w3, w4, w5;
        w0 = (y0 - 3 >= 0) ? src[(size_t)(y0 - 3) * 2048] : NEG;
        w1 = (y0 - 2 >= 0) ? src[(size_t)(y0 - 2) * 2048] : NEG;
        w2 = (y0 - 1 >= 0) ? src[(size_t)(y0 - 1) * 2048] : NEG;
        w3 = src[(size_t)(y0 + 0) * 2048];
        w4 = src[(size_t)(y0 + 1) * 2048];
        w5 = src[(size_t)(y0 + 2) * 2048];
        #pragma unroll 4
        for (int y = 0; y < 16; y++) {
            int yg = y0 + y + 3;
            uint4 nxt = (yg < 64) ? src[(size_t)yg * 2048] : NEG;
            uint4 m = hmax4(hmax4(hmax4(w0, w1), hmax4(w2, w3)),
                            hmax4(hmax4(w4, w5), nxt));
            ym[x * 65 + y * 4 + cq] = m;
            w0 = w1; w1 = w2; w2 = w3; w3 = w4; w4 = w5; w5 = nxt;
        }
    }
    // idx tile
    for (int i = tid; i < 1024; i += 256) {
        int x = i >> 4, yy = i & 15;
        idx_s[i] = g_idxT[(z * 64 + x) * 64 + y0 + yy];
    }
    __syncthreads();

    // ---- phase B: x-window max over ym, 1 LDS.128 per step ----
    {
        int cq = tid & 3, y = (tid >> 2) & 15, xq = tid >> 6;
        int x0 = xq * 16;
        int off = y * 4 + cq;
        uint4 w0, w1, w2, w3, w4, w5;
        w0 = (x0 - 3 >= 0) ? ym[(x0 - 3) * 65 + off] : NEG;
        w1 = (x0 - 2 >= 0) ? ym[(x0 - 2) * 65 + off] : NEG;
        w2 = (x0 - 1 >= 0) ? ym[(x0 - 1) * 65 + off] : NEG;
        w3 = ym[(x0 + 0) * 65 + off];
        w4 = ym[(x0 + 1) * 65 + off];
        w5 = ym[(x0 + 2) * 65 + off];
        #pragma unroll 4
        for (int xx = x0; xx < x0 + 16; xx++) {
            uint4 nxt = (xx + 3 < 64) ? ym[(xx + 3) * 65 + off] : NEG;
            int id = idx_s[xx * 16 + y];
            if (id >= 0) {
                uint4 m = hmax4(hmax4(hmax4(w0, w1), hmax4(w2, w3)),
                                hmax4(hmax4(w4, w5), nxt));
                g_y4[(size_t)id * 32 + cg * 4 + cq] = m;
            }
            w0 = w1; w1 = w2; w2 = w3; w3 = w4; w4 = w5; w5 = nxt;
        }
    }
}

// ===========================================================================
// MLP via mma.sync fp16 (m16n8k16, f32 accum), fragment-major SMEM
// ===========================================================================
__device__ __forceinline__ void mma16(float* c, unsigned a0, unsigned a1,
                                      unsigned a2, unsigned a3,
                                      unsigned b0, unsigned b1) {
    asm("mma.sync.aligned.m16n8k16.row.col.f32.f16.f16.f32 "
        "{%0,%1,%2,%3}, {%4,%5,%6,%7}, {%8,%9}, {%0,%1,%2,%3};"
        : "+f"(c[0]), "+f"(c[1]), "+f"(c[2]), "+f"(c[3])
        : "r"(a0), "r"(a1), "r"(a2), "r"(a3), "r"(b0), "r"(b1));
}

// byte offsets in dynamic smem
#define OFF_XS0 0        // 8KB A-frag (GEMM1)   } aliased by HS (4 x 8KB)
#define OFF_XS1 8192     // 8KB                  }
#define OFF_WS0 16384    // 8KB B-frag (GEMM1)   }
#define OFF_WS1 24576    // 8KB                  }
#define OFF_HS  0
#define OFF_C0  32768    // 8KB B-frag (GEMM2)
#define OFF_C1  40960    // 8KB
#define MLP_SMEM 49152

// A-frag tile (32-k chunk, 128 rows): uint4 slot (mb*2+ks)*32 + lane,
//   components = {A[16mb+g][k16], A[16mb+8+g][k16], same at k16+8}, half2 pairs
// B-frag tile: uint2 slot (nb*2+ks)*32 + lane = {B[8nb+g] at k=2tg,2tg+1 / +8}

__device__ __forceinline__ void compute_chunk(const uint4* __restrict__ A4,
                                              const uint2* __restrict__ B2,
                                              int wm, int wn, int lane,
                                              float acc[2][8][4]) {
    #pragma unroll
    for (int ks = 0; ks < 2; ks++) {
        uint4 a0 = A4[((wm * 2 + 0) * 2 + ks) * 32 + lane];
        uint4 a1 = A4[((wm * 2 + 1) * 2 + ks) * 32 + lane];
        #pragma unroll
        for (int nt = 0; nt < 8; nt++) {
            uint2 b = B2[((wn * 8 + nt) * 2 + ks) * 32 + lane];
            mma16(acc[0][nt], a0.x, a0.y, a0.z, a0.w, b.x, b.y);
            mma16(acc[1][nt], a1.x, a1.y, a1.z, a1.w, b.x, b.y);
        }
    }
}

__device__ __forceinline__ void ldg_X(uint4 v[2], int tid, int row0, int kt) {
    #pragma unroll
    for (int u = 0; u < 2; u++) {
        int id = tid + u * 256;
        int r = id >> 2, c8 = id & 3;
        v[u] = (row0 + r < NPTS)
             ? g_y4[(size_t)(row0 + r) * 32 + kt * 4 + c8]
             : make_uint4(0, 0, 0, 0);
    }
}
__device__ __forceinline__ void sts_X(unsigned* X32, int tid, const uint4 v[2]) {
    #pragma unroll
    for (int u = 0; u < 2; u++) {
        int id = tid + u * 256;
        int r = id >> 2, c8 = id & 3;
        int mb = r >> 4, g = r & 7, rb = (r >> 3) & 1;
        int ksc = c8 >> 1, kbit = c8 & 1;
        int sbase = (mb * 2 + ksc) * 32 + g * 4;
        int comp = rb + 2 * kbit;
        unsigned vv[4] = {v[u].x, v[u].y, v[u].z, v[u].w};
        #pragma unroll
        for (int j = 0; j < 4; j++)
            X32[(sbase + j) * 4 + comp] = vv[j];
    }
}
__device__ __forceinline__ void ldg_W(float4 v[4], int tid,
                                      const float* __restrict__ W, int ldw,
                                      int kt, int ncol0) {
    #pragma unroll
    for (int u = 0; u < 4; u++) {
        int e = tid + u * 256;
        int k = e >> 5, n4 = e & 31;
        v[u] = *(const float4*)(W + (size_t)(kt * 32 + k) * ldw + ncol0 + n4 * 4);
    }
}
__device__ __forceinline__ void sts_W(unsigned short* W16, int tid,
                                      const float4 v[4]) {
    #pragma unroll
    for (int u = 0; u < 4; u++) {
        int e = tid + u * 256;
        int k = e >> 5, n4 = e & 31;
        int ksc = (k >> 4) & 1, kbit = (k & 15) >> 3;
        int tg = (k & 7) >> 1, elem = k & 1;
        float vv[4] = {v[u].x, v[u].y, v[u].z, v[u].w};
        #pragma unroll
        for (int i = 0; i < 4; i++) {
            int n = n4 * 4 + i;
            int slot = ((n >> 3) * 2 + ksc) * 32 + (n & 7) * 4 + tg;
            W16[slot * 4 + kbit * 2 + elem] =
                __half_as_ushort(__float2half_rn(vv[i]));
        }
    }
}

__global__ void __launch_bounds__(256, 2)
mlp_mma_kernel(const float* __restrict__ feats,
               const float* __restrict__ W1,
               const float* __restrict__ W2,
               float* __restrict__ out) {
    extern __shared__ char smb[];
    unsigned*       X32b[2] = {(unsigned*)(smb + OFF_XS0), (unsigned*)(smb + OFF_XS1)};
    unsigned short* W16b[2] = {(unsigned short*)(smb + OFF_WS0),
                               (unsigned short*)(smb + OFF_WS1)};
    unsigned short* C16b[2] = {(unsigned short*)(smb + OFF_C0),
                               (unsigned short*)(smb + OFF_C1)};
    unsigned* HS32 = (unsigned*)(smb + OFF_HS);

    int tid  = threadIdx.x;
    int lane = tid & 31, wid = tid >> 5;
    int wm = wid >> 1, wn = wid & 1;
    int g = lane >> 2, tg = lane & 3;
    int row0 = blockIdx.x * 128;

    uint4  vx[2];
    float4 vw[4];
    float acc[2][8][4];

    // ---------------- GEMM1: H = relu(Y @ W1), K=256, 8 chunks --------------
    #pragma unroll
    for (int mt = 0; mt < 2; mt++)
        #pragma unroll
        for (int nt = 0; nt < 8; nt++)
            #pragma unroll
            for (int q = 0; q < 4; q++) acc[mt][nt][q] = 0.f;

    ldg_X(vx, tid, row0, 0);
    ldg_W(vw, tid, W1, RDIM, 0, 0);
    sts_X(X32b[0], tid, vx);
    sts_W(W16b[0], tid, vw);
    __syncthreads();

    for (int kt = 0; kt < 8; kt++) {
        if (kt < 7) {
            ldg_X(vx, tid, row0, kt + 1);
            ldg_W(vw, tid, W1, RDIM, kt + 1, 0);
        }
        compute_chunk((const uint4*)X32b[kt & 1], (const uint2*)W16b[kt & 1],
                      wm, wn, lane, acc);
        if (kt < 7) {
            sts_X(X32b[(kt + 1) & 1], tid, vx);
            sts_W(W16b[(kt + 1) & 1], tid, vw);
        }
        __syncthreads();
    }

    // relu -> HS in fp16 A-frag layout (aliases XS/WS; all reads done)
    #pragma unroll
    for (int mt = 0; mt < 2; mt++) {
        #pragma unroll
        for (int nt = 0; nt < 8; nt++) {
            int mb = wm * 2 + mt;
            int kc = wn * 2 + (nt >> 2);
            unsigned* Hc = HS32 + kc * 2048;
            int slot = (mb * 2 + ((nt & 3) >> 1)) * 32 + g * 4 + tg;
            Hc[slot * 4 + 2 * (nt & 1)] =
                pack2(fmaxf(acc[mt][nt][0], 0.f), fmaxf(acc[mt][nt][1], 0.f));
            Hc[slot * 4 + 1 + 2 * (nt & 1)] =
                pack2(fmaxf(acc[mt][nt][2], 0.f), fmaxf(acc[mt][nt][3], 0.f));
        }
    }
    __syncthreads();

    // ------------- GEMM2: O = H @ W2 (K=128), two 128-col halves ------------
    for (int half = 0; half < 2; half++) {
        #pragma unroll
        for (int mt = 0; mt < 2; mt++)
            #pragma unroll
            for (int nt = 0; nt < 8; nt++)
                #pragma unroll
                for (int q = 0; q < 4; q++) acc[mt][nt][q] = 0.f;

        ldg_W(vw, tid, W2, C, 0, half * 128);
        sts_W(C16b[0], tid, vw);
        __syncthreads();

        for (int kc = 0; kc < 4; kc++) {
            if (kc < 3) ldg_W(vw, tid, W2, C, kc + 1, half * 128);
            compute_chunk((const uint4*)(HS32 + kc * 2048),
                          (const uint2*)C16b[kc & 1], wm, wn, lane, acc);
            if (kc < 3) sts_W(C16b[(kc + 1) & 1], tid, vw);
            __syncthreads();
        }

        // epilogue: out = feats * sigmoid(acc)
        #pragma unroll
        for (int mt = 0; mt < 2; mt++) {
            #pragma unroll
            for (int nt = 0; nt < 8; nt++) {
                int rr = wm * 32 + mt * 16 + g;
                int cc = half * 128 + wn * 64 + nt * 8 + 2 * tg;
                #pragma unroll
                for (int h = 0; h < 2; h++) {
                    int row = row0 + rr + h * 8;
                    if (row < NPTS) {
                        float z0 = acc[mt][nt][h * 2 + 0];
                        float z1 = acc[mt][nt][h * 2 + 1];
                        float2 fv = *(const float2*)(feats + (size_t)row * C + cc);
                        float2 o;
                        o.x = fv.x / (1.f + __expf(-z0));
                        o.y = fv.y / (1.f + __expf(-z1));
                        *(float2*)(out + (size_t)row * C + cc) = o;
                    }
                }
            }
        }
    }
}

// ===========================================================================
extern "C" void kernel_launch(void* const* d_in, const int* in_sizes, int n_in,
                              void* d_out, int out_size) {
    const float* feats  = (const float*)d_in[0];
    const int*   coords = (const int*)d_in[1];
    const float* W1     = (const float*)d_in[2];
    const float* W2     = (const float*)d_in[3];
    float*       out    = (float*)d_out;

    init_idx_kernel<<<GRID_VOX/256, 256>>>();
    scatter_idx_kernel<<<(NPTS + 255)/256, 256>>>(coords);

    dim3 zt(32, 8);
    pool_z_kernel<<<D*D/8, zt>>>(feats);

    cudaFuncSetAttribute(pool_yx_kernel,
                         cudaFuncAttributeMaxDynamicSharedMemorySize, POOL_SMEM);
    pool_yx_kernel<<<64 * 8 * 4, 256, POOL_SMEM>>>();

    cudaFuncSetAttribute(mlp_mma_kernel,
                         cudaFuncAttributeMaxDynamicSharedMemorySize, MLP_SMEM);
    mlp_mma_kernel<<<(NPTS + 127)/128, 256, MLP_SMEM>>>(feats, W1, W2, out);
}